// round 7
// baseline (speedup 1.0000x reference)
#include <cuda_runtime.h>
#include <cuda_bf16.h>

// LatentMap, R7: two-kernel phase split.
//
// Kernel A (scatter phase): one thread per query. Loads position (coalesced),
//   gathers neighbor_map (scattered 16B) and 4 point positions (scattered 8B),
//   computes normalized inverse-distance weights, writes nb(int4) + w(float4)
//   to 32MB device scratch with coalesced STG.128.
//
// Kernel B (blend phase): R6's proven phase-2. Warp sweeps 32 queries 4 at a
//   time; lane -> (query sub = lane>>3, feature quad = (lane&7)*4). Per
//   iteration: 2 broadcast 64B-span loads of nb/w from scratch, 4 coalesced
//   LDG.128 embedding gathers (full 128B lines), 1 STG.128 (512B), FFMA.
//
// Rationale: R4-R6 showed L1 saturating at ~74% SOL regardless of occupancy
// (43..57 warps/SM) -> the limiter is the heterogeneous wavefront mix
// (replay-heavy scatters + streams in the same pipe). Homogeneous kernels
// should each run at higher L1 efficiency, beating the +64MB scratch cost.

#define IMG 1024
#define EMB 32
#define N_Q_MAX (1 << 20)

__device__ int4   g_nb[N_Q_MAX];
__device__ float4 g_w [N_Q_MAX];

// ---------------------------------------------------------------- Kernel A
__global__ void __launch_bounds__(256) weights_kernel(
    const float2* __restrict__ position,      // [N_Q]
    const float2* __restrict__ positions,     // [N_PTS]
    const int4*   __restrict__ neighbor_map,  // [IMG*IMG]
    int n_q)
{
    const int q = blockIdx.x * blockDim.x + threadIdx.x;
    if (q >= n_q) return;

    const float2 p = position[q];
    const int ix = (int)floorf(p.x);
    const int iy = (int)floorf(p.y);
    const int4 nb = neighbor_map[ix * IMG + iy];

    const float2 p0 = positions[nb.x];
    const float2 p1 = positions[nb.y];
    const float2 p2 = positions[nb.z];
    const float2 p3 = positions[nb.w];

    const float fx = (float)ix, fy = (float)iy;
    float dx, dy;
    dx = p0.x - fx; dy = p0.y - fy;
    const float d0 = sqrtf(dx * dx + dy * dy);
    dx = p1.x - fx; dy = p1.y - fy;
    const float d1 = sqrtf(dx * dx + dy * dy);
    dx = p2.x - fx; dy = p2.y - fy;
    const float d2 = sqrtf(dx * dx + dy * dy);
    dx = p3.x - fx; dy = p3.y - fy;
    const float d3 = sqrtf(dx * dx + dy * dy);

    const float rs = 1.0f / (d0 + d1 + d2 + d3 + 1e-8f);
    float4 w;
    w.x = 1.0f - d0 * rs;
    w.y = 1.0f - d1 * rs;
    w.z = 1.0f - d2 * rs;
    w.w = 1.0f - d3 * rs;

    g_nb[q] = nb;   // coalesced STG.128
    g_w [q] = w;    // coalesced STG.128
}

// ---------------------------------------------------------------- Kernel B
#define WARPS_PER_BLOCK 8
#define QUERIES_PER_WARP 32

__global__ void __launch_bounds__(WARPS_PER_BLOCK * 32, 8) blend_kernel(
    const float*  __restrict__ embeddings,    // [N_PTS, EMB]
    const float*  __restrict__ harmonics,     // [EMB]
    float*        __restrict__ out,           // [N_Q, EMB]
    int n_q)
{
    const int warp = threadIdx.x >> 5;
    const int lane = threadIdx.x & 31;
    const int qbase = (blockIdx.x * WARPS_PER_BLOCK + warp) * QUERIES_PER_WARP;

    const int sub = lane >> 3;        // 0..3
    const int fq  = (lane & 7) * 4;   // 0,4,...,28

    const float4 h4 = *(const float4*)&harmonics[fq];
    const bool full_tile = (qbase + QUERIES_PER_WARP) <= n_q;

    if (full_tile) {
        #pragma unroll
        for (int i = 0; i < QUERIES_PER_WARP; i += 4) {
            const int q = qbase + i + sub;
            const int4   nb = __ldg(&g_nb[q]);   // 64B span, 1 wf, broadcast
            const float4 w  = __ldg(&g_w [q]);   // 64B span, 1 wf, broadcast

            const float4 e0 = __ldg((const float4*)&embeddings[(long)nb.x * EMB + fq]);
            const float4 e1 = __ldg((const float4*)&embeddings[(long)nb.y * EMB + fq]);
            const float4 e2 = __ldg((const float4*)&embeddings[(long)nb.z * EMB + fq]);
            const float4 e3 = __ldg((const float4*)&embeddings[(long)nb.w * EMB + fq]);

            float4 acc;
            acc.x = w.x * e0.x + w.y * e1.x + w.z * e2.x + w.w * e3.x;
            acc.y = w.x * e0.y + w.y * e1.y + w.z * e2.y + w.w * e3.y;
            acc.z = w.x * e0.z + w.y * e1.z + w.z * e2.z + w.w * e3.z;
            acc.w = w.x * e0.w + w.y * e1.w + w.z * e2.w + w.w * e3.w;

            acc.x *= h4.x; acc.y *= h4.y; acc.z *= h4.z; acc.w *= h4.w;

            *(float4*)&out[(long)q * EMB + fq] = acc;
        }
    } else {
        #pragma unroll
        for (int i = 0; i < QUERIES_PER_WARP; i += 4) {
            const int q = qbase + i + sub;
            if (q < n_q) {
                const int4   nb = __ldg(&g_nb[q]);
                const float4 w  = __ldg(&g_w [q]);

                const float4 e0 = __ldg((const float4*)&embeddings[(long)nb.x * EMB + fq]);
                const float4 e1 = __ldg((const float4*)&embeddings[(long)nb.y * EMB + fq]);
                const float4 e2 = __ldg((const float4*)&embeddings[(long)nb.z * EMB + fq]);
                const float4 e3 = __ldg((const float4*)&embeddings[(long)nb.w * EMB + fq]);

                float4 acc;
                acc.x = w.x * e0.x + w.y * e1.x + w.z * e2.x + w.w * e3.x;
                acc.y = w.x * e0.y + w.y * e1.y + w.z * e2.y + w.w * e3.y;
                acc.z = w.x * e0.z + w.y * e1.z + w.z * e2.z + w.w * e3.z;
                acc.w = w.x * e0.w + w.y * e1.w + w.z * e2.w + w.w * e3.w;

                acc.x *= h4.x; acc.y *= h4.y; acc.z *= h4.z; acc.w *= h4.w;

                *(float4*)&out[(long)q * EMB + fq] = acc;
            }
        }
    }
}

extern "C" void kernel_launch(void* const* d_in, const int* in_sizes, int n_in,
                              void* d_out, int out_size)
{
    const float2* position     = (const float2*)d_in[0];
    const float2* positions    = (const float2*)d_in[1];
    const int4*   neighbor_map = (const int4*)d_in[2];
    const float*  embeddings   = (const float*)d_in[3];
    const float*  harmonics    = (const float*)d_in[4];
    float*        out          = (float*)d_out;

    int n_q = in_sizes[0] / 2;
    if (n_q > N_Q_MAX) n_q = N_Q_MAX;  // fixed-shape problem: N_Q = 1<<20

    // Kernel A: scatter phase (1 thread/query)
    {
        const int block = 256;
        const int grid = (n_q + block - 1) / block;
        weights_kernel<<<grid, block>>>(position, positions, neighbor_map, n_q);
    }
    // Kernel B: blend phase (1 warp per 32 queries)
    {
        const int queries_per_block = WARPS_PER_BLOCK * QUERIES_PER_WARP; // 256
        const int grid = (n_q + queries_per_block - 1) / queries_per_block;
        blend_kernel<<<grid, WARPS_PER_BLOCK * 32>>>(embeddings, harmonics, out, n_q);
    }
}

// round 8
// speedup vs baseline: 1.1811x; 1.1811x over previous
#include <cuda_runtime.h>
#include <cuda_bf16.h>

// LatentMap, warp-cooperative two-phase fused kernel (R6 structure).
//
// Phase 1: lane l computes per-query scalars (neighbor indices + normalized
//          inverse-distance weights) for query qbase + l, once, -> smem.
// Phase 2: warp sweeps its 32 queries 4 at a time; lane -> (query sub =
//          lane>>3, feature quad = (lane&7)*4): 2 LDS.128, 4 coalesced
//          LDG.128 gathers, 1 STG.128 spanning 512B, ~20 FFMA.
//
// R8: identical to R6 except the phase-2 loop unroll is capped at 2 to
// reduce per-warp front-batched LDG.128 count (MLP_p1 ~16 -> ~8) and with
// it cross-CTA L1tex-queue contention at occ=8 (B300 spread model). Cross-
// warp parallelism (57 warps/SM) keeps the L1 pipe fed.

#define IMG 1024
#define EMB 32
#define WARPS_PER_BLOCK 8
#define QUERIES_PER_WARP 32

__global__ void __launch_bounds__(WARPS_PER_BLOCK * 32, 8) latent_map_kernel(
    const float2* __restrict__ position,      // [N_Q]
    const float2* __restrict__ positions,     // [N_PTS]
    const int4*   __restrict__ neighbor_map,  // [IMG*IMG]
    const float*  __restrict__ embeddings,    // [N_PTS, EMB]
    const float*  __restrict__ harmonics,     // [EMB]
    float*        __restrict__ out,           // [N_Q, EMB]
    int n_q)
{
    __shared__ int4   s_nb[WARPS_PER_BLOCK][QUERIES_PER_WARP];
    __shared__ float4 s_w [WARPS_PER_BLOCK][QUERIES_PER_WARP];

    const int warp = threadIdx.x >> 5;
    const int lane = threadIdx.x & 31;
    const int qbase = (blockIdx.x * WARPS_PER_BLOCK + warp) * QUERIES_PER_WARP;

    const bool full_tile = (qbase + QUERIES_PER_WARP) <= n_q;

    // ---- Phase 1: one query per lane, scalar work done exactly once ----
    {
        const int q = qbase + lane;
        if (full_tile || q < n_q) {
            const float2 p = position[q];
            const int ix = (int)floorf(p.x);
            const int iy = (int)floorf(p.y);
            const int4 nb = neighbor_map[ix * IMG + iy];

            const float2 p0 = positions[nb.x];
            const float2 p1 = positions[nb.y];
            const float2 p2 = positions[nb.z];
            const float2 p3 = positions[nb.w];

            const float fx = (float)ix, fy = (float)iy;
            float dx, dy;
            dx = p0.x - fx; dy = p0.y - fy;
            const float d0 = sqrtf(dx * dx + dy * dy);
            dx = p1.x - fx; dy = p1.y - fy;
            const float d1 = sqrtf(dx * dx + dy * dy);
            dx = p2.x - fx; dy = p2.y - fy;
            const float d2 = sqrtf(dx * dx + dy * dy);
            dx = p3.x - fx; dy = p3.y - fy;
            const float d3 = sqrtf(dx * dx + dy * dy);

            const float rs = 1.0f / (d0 + d1 + d2 + d3 + 1e-8f);
            float4 w;
            w.x = 1.0f - d0 * rs;
            w.y = 1.0f - d1 * rs;
            w.z = 1.0f - d2 * rs;
            w.w = 1.0f - d3 * rs;

            s_nb[warp][lane] = nb;
            s_w [warp][lane] = w;
        }
    }
    __syncwarp();

    // ---- Phase 2: 4 queries per iteration; lane -> (query sub, feature quad)
    const int sub = lane >> 3;        // 0..3
    const int fq  = (lane & 7) * 4;   // 0,4,...,28

    const float4 h4 = *(const float4*)&harmonics[fq];

    if (full_tile) {
        // Hot path: no per-iteration predicates. Unroll capped at 2 to limit
        // front-batched LDGs (L1tex queue contention at high occupancy).
        #pragma unroll 2
        for (int i = 0; i < QUERIES_PER_WARP; i += 4) {
            const int4   nb = s_nb[warp][i + sub];  // LDS.128
            const float4 w  = s_w [warp][i + sub];  // LDS.128

            const float4 e0 = __ldg((const float4*)&embeddings[(long)nb.x * EMB + fq]);
            const float4 e1 = __ldg((const float4*)&embeddings[(long)nb.y * EMB + fq]);
            const float4 e2 = __ldg((const float4*)&embeddings[(long)nb.z * EMB + fq]);
            const float4 e3 = __ldg((const float4*)&embeddings[(long)nb.w * EMB + fq]);

            float4 acc;
            acc.x = w.x * e0.x + w.y * e1.x + w.z * e2.x + w.w * e3.x;
            acc.y = w.x * e0.y + w.y * e1.y + w.z * e2.y + w.w * e3.y;
            acc.z = w.x * e0.z + w.y * e1.z + w.z * e2.z + w.w * e3.z;
            acc.w = w.x * e0.w + w.y * e1.w + w.z * e2.w + w.w * e3.w;

            acc.x *= h4.x; acc.y *= h4.y; acc.z *= h4.z; acc.w *= h4.w;

            *(float4*)&out[(long)(qbase + i + sub) * EMB + fq] = acc;
        }
    } else {
        #pragma unroll 2
        for (int i = 0; i < QUERIES_PER_WARP; i += 4) {
            const int q = qbase + i + sub;
            if (q < n_q) {
                const int4   nb = s_nb[warp][i + sub];
                const float4 w  = s_w [warp][i + sub];

                const float4 e0 = __ldg((const float4*)&embeddings[(long)nb.x * EMB + fq]);
                const float4 e1 = __ldg((const float4*)&embeddings[(long)nb.y * EMB + fq]);
                const float4 e2 = __ldg((const float4*)&embeddings[(long)nb.z * EMB + fq]);
                const float4 e3 = __ldg((const float4*)&embeddings[(long)nb.w * EMB + fq]);

                float4 acc;
                acc.x = w.x * e0.x + w.y * e1.x + w.z * e2.x + w.w * e3.x;
                acc.y = w.x * e0.y + w.y * e1.y + w.z * e2.y + w.w * e3.y;
                acc.z = w.x * e0.z + w.y * e1.z + w.z * e2.z + w.w * e3.z;
                acc.w = w.x * e0.w + w.y * e1.w + w.z * e2.w + w.w * e3.w;

                acc.x *= h4.x; acc.y *= h4.y; acc.z *= h4.z; acc.w *= h4.w;

                *(float4*)&out[(long)q * EMB + fq] = acc;
            }
        }
    }
}

extern "C" void kernel_launch(void* const* d_in, const int* in_sizes, int n_in,
                              void* d_out, int out_size)
{
    const float2* position     = (const float2*)d_in[0];
    const float2* positions    = (const float2*)d_in[1];
    const int4*   neighbor_map = (const int4*)d_in[2];
    const float*  embeddings   = (const float*)d_in[3];
    const float*  harmonics    = (const float*)d_in[4];
    float*        out          = (float*)d_out;

    const int n_q = in_sizes[0] / 2;
    const int queries_per_block = WARPS_PER_BLOCK * QUERIES_PER_WARP; // 256
    const int grid = (n_q + queries_per_block - 1) / queries_per_block;
    latent_map_kernel<<<grid, WARPS_PER_BLOCK * 32>>>(
        position, positions, neighbor_map, embeddings, harmonics, out, n_q);
}